// round 4
// baseline (speedup 1.0000x reference)
#include <cuda_runtime.h>
#include <cuda_bf16.h>
#include <math.h>

#define DIN 1024
#define D   256
#define DG  128
#define DB  64
#define NL1 8
#define NL2 32
#define BATCH 16
#define TLEN 2048
#define MROWS (BATCH*TLEN)

__device__ float g_U[MROWS*D];
__device__ float g_gin[BATCH*DIN];
__device__ int   g_idx1[BATCH];
__device__ float g_Wc[DB*D];
__device__ float g_bc[DB];
__device__ float g_nck[NL1*NL2*DB];
__device__ float g_snck[NL1*NL2];
__device__ float g_Mall[NL1*D*NL2];
__device__ float g_dall[NL1*NL2];
__device__ float g_table[NL1*NL2*D];
// transposed weights
__device__ float g_Wl1T[DIN*D];
__device__ float g_Wg1T[DIN*D];
__device__ float g_Wg2T[D*DG];
__device__ float g_WpT[DG*DG];
__device__ float g_WfbT[DB*D];
__device__ float g_WfT[(D+DG)*D];
// ginstats partials: s then q
__device__ float g_part[2*BATCH*4*DIN];
// repair list
__device__ int g_rcount;
__device__ int g_rlist[MROWS];

__device__ __forceinline__ void blockLN256(float v, int tid, float* sred,
                                           float& mean, float& rinv) {
    __syncthreads();
    float s = v, q = v*v;
#pragma unroll
    for (int off = 16; off; off >>= 1) {
        s += __shfl_xor_sync(0xffffffffu, s, off);
        q += __shfl_xor_sync(0xffffffffu, q, off);
    }
    if ((tid & 31) == 0) { sred[tid >> 5] = s; sred[8 + (tid >> 5)] = q; }
    __syncthreads();
    float ts = 0.f, tq = 0.f;
#pragma unroll
    for (int w = 0; w < 8; w++) { ts += sred[w]; tq += sred[8 + w]; }
    mean = ts * (1.f / 256.f);
    float var = tq * (1.f / 256.f) - mean * mean;
    rinv = rsqrtf(fmaxf(var, 0.f) + 1e-5f);
}

__global__ void k_init() { if (threadIdx.x == 0) g_rcount = 0; }

// generic transpose in[R][C] -> out[C][R]; R,C multiples of 32
__global__ void k_transpose(const float* __restrict__ in, float* __restrict__ out,
                            int R, int C) {
    __shared__ float t[32][33];
    int cb = blockIdx.x * 32, rb = blockIdx.y * 32;
    int x = cb + threadIdx.x;
#pragma unroll
    for (int j = 0; j < 32; j += 8) {
        int r = rb + threadIdx.y + j;
        t[threadIdx.y + j][threadIdx.x] = in[(size_t)r * C + x];
    }
    __syncthreads();
    int ox = rb + threadIdx.x;
#pragma unroll
    for (int j = 0; j < 32; j += 8) {
        int c = cb + threadIdx.y + j;
        out[(size_t)c * R + ox] = t[threadIdx.x][threadIdx.y + j];
    }
}

__global__ void k_wc(const float* __restrict__ Wtb, const float* __restrict__ Wl2,
                     const float* __restrict__ bl2, const float* __restrict__ btb) {
    __shared__ float sw[D];
    int i = blockIdx.x, j = threadIdx.x;
    sw[j] = Wtb[i*D + j];
    __syncthreads();
    float acc = 0.f;
#pragma unroll 4
    for (int r = 0; r < D; r++) acc += sw[r] * Wl2[r*D + j];
    g_Wc[i*D + j] = acc;
    if (j == 0) {
        float a = btb[i];
        for (int r = 0; r < D; r++) a += sw[r] * bl2[r];
        g_bc[i] = a;
    }
}

__global__ void k_nck(const float* __restrict__ cb2) {
    __shared__ float sred[4];
    int bk = blockIdx.x, t = threadIdx.x;
    float v = cb2[bk*DB + t];
    float q = v*v;
#pragma unroll
    for (int off = 16; off; off >>= 1) q += __shfl_xor_sync(0xffffffffu, q, off);
    if ((t & 31) == 0) sred[t >> 5] = q;
    __syncthreads();
    float nrm = sqrtf(sred[0] + sred[1]);
    float nv = v / fmaxf(nrm, 1e-12f);
    g_nck[bk*DB + t] = nv;
    float s = nv;
#pragma unroll
    for (int off = 16; off; off >>= 1) s += __shfl_xor_sync(0xffffffffu, s, off);
    if ((t & 31) == 0) sred[2 + (t >> 5)] = s;
    __syncthreads();
    if (t == 0) g_snck[bk] = sred[2] + sred[3];
}

__global__ void k_Md() {
    __shared__ float sN[NL2*65];
    int i = blockIdx.x, tid = threadIdx.x;
    int k = tid & 31, cl = tid >> 5;
    int c = blockIdx.y * 8 + cl;
    for (int t = tid; t < NL2*DB; t += 256) {
        int kk = t / DB, rr = t % DB;
        sN[kk*65 + rr] = g_nck[i*NL2*DB + t];
    }
    __syncthreads();
    float acc = 0.f, cs = 0.f;
#pragma unroll 4
    for (int r = 0; r < DB; r++) {
        float wv = g_Wc[r*D + c];
        acc += wv * sN[k*65 + r];
        cs  += wv;
    }
    float sn = g_snck[i*NL2 + k];
    g_Mall[i*(D*NL2) + c*NL2 + k] = acc - cs * sn * (1.f/DB);
    if (blockIdx.y == 0 && cl == 0) {
        float dv = 0.f, bs = 0.f;
        for (int r = 0; r < DB; r++) {
            float b = g_bc[r];
            dv += b * sN[k*65 + r];
            bs += b;
        }
        g_dall[i*NL2 + k] = dv - bs * (1.f/DB) * sn;
    }
}

// table: coalesced via transposed weights
__global__ void k_table(const float* __restrict__ cb2, const float* __restrict__ bfb,
                        const float* __restrict__ cb1, const float* __restrict__ bf) {
    __shared__ float se[DB];
    __shared__ float sl[D];
    __shared__ float sc1[DG];
    __shared__ float sred[16];
    int bid = blockIdx.x;
    int i = bid >> 5;
    int j = threadIdx.x;
    if (j < DB) se[j] = cb2[bid*DB + j];
    if (j >= 128) sc1[j - 128] = cb1[i*DG + (j - 128)];
    __syncthreads();
    float a = bfb[j];
#pragma unroll 4
    for (int r = 0; r < DB; r++) a += se[r] * g_WfbT[r*D + j];
    float mean, rinv;
    blockLN256(a, j, sred, mean, rinv);
    sl[j] = (a - mean) * rinv;
    __syncthreads();
    float o = bf[j];
#pragma unroll 4
    for (int r = 0; r < D; r++) o += sl[r] * g_WfT[r*D + j];
#pragma unroll 4
    for (int r = 0; r < DG; r++) o += sc1[r] * g_WfT[(D + r)*D + j];
    blockLN256(o, j, sred, mean, rinv);
    g_table[bid*D + j] = fmaxf((o - mean) * rinv, 0.f);
}

// ginstats stage 1: partial sums over t-quarters
__global__ void k_gs1(const float* __restrict__ x) {
    int bx = blockIdx.x;
    int b = bx >> 4, dc = (bx >> 2) & 3, tc = bx & 3;
    int d = dc * 256 + threadIdx.x;
    const float* p = x + ((size_t)b * TLEN + tc * 512) * DIN + d;
    float s = 0.f, q = 0.f;
    for (int t = 0; t < 512; t++) {
        float v = p[(size_t)t * DIN];
        s += v; q += v * v;
    }
    g_part[(b*4 + tc)*DIN + d] = s;
    g_part[BATCH*4*DIN + (b*4 + tc)*DIN + d] = q;
}

__global__ void k_gs2() {
    int b = blockIdx.x >> 2, dc = blockIdx.x & 3;
    int d = dc * 256 + threadIdx.x;
    float s = 0.f, q = 0.f;
#pragma unroll
    for (int tc = 0; tc < 4; tc++) {
        s += g_part[(b*4 + tc)*DIN + d];
        q += g_part[BATCH*4*DIN + (b*4 + tc)*DIN + d];
    }
    float mean = s * (1.f / TLEN);
    float var = (q - s * s * (1.f / TLEN)) * (1.f / (TLEN - 1));
    g_gin[b*DIN + d] = mean + sqrtf(fmaxf(var, 0.f));
}

__global__ void k_global(const float* __restrict__ bg1, const float* __restrict__ bg2,
                         const float* __restrict__ bp,  const float* __restrict__ cb1) {
    __shared__ float sg[DIN];
    __shared__ float sh[D];
    __shared__ float sgp[DG];
    __shared__ float sz[DG];
    __shared__ float sred[16];
    __shared__ float slog[NL1];
    int b = blockIdx.x, j = threadIdx.x;
    for (int t = j; t < DIN; t += 256) sg[t] = g_gin[b*DIN + t];
    __syncthreads();
    float a = bg1[j];
#pragma unroll 4
    for (int r = 0; r < DIN; r++) a += sg[r] * g_Wg1T[r*D + j];
    float mean, rinv;
    blockLN256(a, j, sred, mean, rinv);
    sh[j] = fmaxf((a - mean) * rinv, 0.f);
    __syncthreads();
    if (j < DG) {
        float g2 = bg2[j];
#pragma unroll 4
        for (int r = 0; r < D; r++) g2 += sh[r] * g_Wg2T[r*DG + j];
        sgp[j] = g2;
    }
    __syncthreads();
    if (j < DG) {
        float z = bp[j];
#pragma unroll 4
        for (int r = 0; r < DG; r++) z += sgp[r] * g_WpT[r*DG + j];
        sz[j] = z;
    }
    __syncthreads();
    {
        float zv = (j < DG) ? sz[j] : 0.f;
        float s = zv;
#pragma unroll
        for (int off = 16; off; off >>= 1) s += __shfl_xor_sync(0xffffffffu, s, off);
        if ((j & 31) == 0) sred[j >> 5] = s;
        __syncthreads();
    }
    float meanz = (sred[0]+sred[1]+sred[2]+sred[3]+sred[4]+sred[5]+sred[6]+sred[7]) * (1.f/DG);
    if (j < NL1) {
        float dz = 0.f, cs = 0.f, nn = 0.f;
        const float* cr = cb1 + j*DG;
        for (int r = 0; r < DG; r++) {
            float cv = cr[r];
            dz += sz[r]*cv; cs += cv; nn += cv*cv;
        }
        slog[j] = (dz - meanz*cs) / fmaxf(sqrtf(nn), 1e-12f);
    }
    __syncthreads();
    if (j == 0) {
        float best = slog[0]; int bi = 0;
        for (int t = 1; t < NL1; t++) if (slog[t] > best) { best = slog[t]; bi = t; }
        g_idx1[b] = bi;
    }
}

// ---------------- tensor-core GEMM: u = x @ Wl1.T + bl1, bf16 split-3 ----------------
__device__ __forceinline__ void ldsm4(unsigned& r0, unsigned& r1, unsigned& r2, unsigned& r3,
                                      const __nv_bfloat16* p) {
    unsigned a = (unsigned)__cvta_generic_to_shared(p);
    asm volatile("ldmatrix.sync.aligned.m8n8.x4.shared.b16 {%0,%1,%2,%3}, [%4];\n"
        : "=r"(r0), "=r"(r1), "=r"(r2), "=r"(r3) : "r"(a));
}
__device__ __forceinline__ void mma16816(float* c, const unsigned* a, unsigned b0, unsigned b1) {
    asm volatile("mma.sync.aligned.m16n8k16.row.col.f32.bf16.bf16.f32 "
        "{%0,%1,%2,%3},{%4,%5,%6,%7},{%8,%9},{%0,%1,%2,%3};\n"
        : "+f"(c[0]), "+f"(c[1]), "+f"(c[2]), "+f"(c[3])
        : "r"(a[0]), "r"(a[1]), "r"(a[2]), "r"(a[3]), "r"(b0), "r"(b1));
}
__device__ __forceinline__ void cvt4(__nv_bfloat16* hi, __nv_bfloat16* lo, float4 v) {
    __nv_bfloat16 h0 = __float2bfloat16(v.x);
    __nv_bfloat16 h1 = __float2bfloat16(v.y);
    __nv_bfloat16 h2 = __float2bfloat16(v.z);
    __nv_bfloat16 h3 = __float2bfloat16(v.w);
    hi[0] = h0; hi[1] = h1; hi[2] = h2; hi[3] = h3;
    lo[0] = __float2bfloat16(v.x - __bfloat162float(h0));
    lo[1] = __float2bfloat16(v.y - __bfloat162float(h1));
    lo[2] = __float2bfloat16(v.z - __bfloat162float(h2));
    lo[3] = __float2bfloat16(v.w - __bfloat162float(h3));
}

#define SMA 40      // padded bf16 stride
#define STG 15360   // bf16 per stage

__global__ __launch_bounds__(256, 2)
void k_gemm(const float* __restrict__ A, const float* __restrict__ Bm,
            const float* __restrict__ bias) {
    extern __shared__ __align__(16) unsigned char dynsm[];
    __nv_bfloat16* sm = (__nv_bfloat16*)dynsm;
    const int K = DIN;
    int tid = threadIdx.x;
    int lane = tid & 31, wid = tid >> 5;
    int wm = wid >> 1, wn = wid & 1;       // 4x2 warp grid, warp tile 32x32
    // global staging mapping
    int arow = tid >> 1, as0 = (tid & 1) * 4;       // A: 4 float4 at slots as0..as0+3
    int brow = tid >> 2, bs0 = tid & 3;             // B: 2 float4 at slots bs0, bs0+4
    const float* Ag = A  + (size_t)(blockIdx.y * 128 + arow) * K;
    const float* Bg = Bm + (size_t)(blockIdx.x * 64 + brow) * K;

    float acc[2][4][4];
#pragma unroll
    for (int m = 0; m < 2; m++)
#pragma unroll
        for (int n = 0; n < 4; n++)
#pragma unroll
            for (int e = 0; e < 4; e++) acc[m][n][e] = 0.f;

    // prologue: stage 0
    {
        __nv_bfloat16* Ah = sm; __nv_bfloat16* Al = sm + 5120;
        __nv_bfloat16* Bh = sm + 10240; __nv_bfloat16* Bl = sm + 12800;
#pragma unroll
        for (int i = 0; i < 4; i++) {
            float4 v = *(const float4*)(Ag + (as0 + i) * 4);
            cvt4(Ah + arow*SMA + (as0+i)*4, Al + arow*SMA + (as0+i)*4, v);
        }
#pragma unroll
        for (int i = 0; i < 2; i++) {
            int s = bs0 + i*4;
            float4 v = *(const float4*)(Bg + s * 4);
            cvt4(Bh + brow*SMA + s*4, Bl + brow*SMA + s*4, v);
        }
    }
    __syncthreads();

    float4 pa[4], pb[2];
    for (int kt = 0; kt < 32; kt++) {
        if (kt < 31) {
            int ko = (kt + 1) * 32;
#pragma unroll
            for (int i = 0; i < 4; i++) pa[i] = *(const float4*)(Ag + ko + (as0+i)*4);
#pragma unroll
            for (int i = 0; i < 2; i++) pb[i] = *(const float4*)(Bg + ko + (bs0 + i*4)*4);
        }
        __nv_bfloat16* Ah = sm + (kt & 1) * STG;
        __nv_bfloat16* Al = Ah + 5120;
        __nv_bfloat16* Bh = Ah + 10240;
        __nv_bfloat16* Bl = Ah + 12800;
#pragma unroll
        for (int k16 = 0; k16 < 2; k16++) {
            int col = k16*16 + (lane >> 4) * 8;
            int arw = wm*32 + (lane & 15);
            int brw = wn*32 + (lane & 15);
            unsigned ah[2][4], al[2][4], bh[2][4], bl[2][4];
            ldsm4(ah[0][0], ah[0][1], ah[0][2], ah[0][3], Ah + arw*SMA + col);
            ldsm4(ah[1][0], ah[1][1], ah[1][2], ah[1][3], Ah + (arw+16)*SMA + col);
            ldsm4(al[0][0], al[0][1], al[0][2], al[0][3], Al + arw*SMA + col);
            ldsm4(al[1][0], al[1][1], al[1][2], al[1][3], Al + (arw+16)*SMA + col);
            ldsm4(bh[0][0], bh[0][1], bh[0][2], bh[0][3], Bh + brw*SMA + col);
            ldsm4(bh[1][0], bh[1][1], bh[1][2], bh[1][3], Bh + (brw+16)*SMA + col);
            ldsm4(bl[0][0], bl[0][1], bl[0][2], bl[0][3], Bl + brw*SMA + col);
            ldsm4(bl[1][0], bl[1][1], bl[1][2], bl[1][3], Bl + (brw+16)*SMA + col);
#pragma unroll
            for (int m = 0; m < 2; m++)
#pragma unroll
                for (int n = 0; n < 4; n++) {
                    int g = n >> 1, o = n & 1;
                    mma16816(acc[m][n], ah[m], bh[g][o], bh[g][o+2]);
                    mma16816(acc[m][n], ah[m], bl[g][o], bl[g][o+2]);
                    mma16816(acc[m][n], al[m], bh[g][o], bh[g][o+2]);
                }
        }
        if (kt < 31) {
            __nv_bfloat16* nAh = sm + ((kt+1) & 1) * STG;
            __nv_bfloat16* nAl = nAh + 5120;
            __nv_bfloat16* nBh = nAh + 10240;
            __nv_bfloat16* nBl = nAh + 12800;
#pragma unroll
            for (int i = 0; i < 4; i++)
                cvt4(nAh + arow*SMA + (as0+i)*4, nAl + arow*SMA + (as0+i)*4, pa[i]);
#pragma unroll
            for (int i = 0; i < 2; i++) {
                int s = bs0 + i*4;
                cvt4(nBh + brow*SMA + s*4, nBl + brow*SMA + s*4, pb[i]);
            }
            __syncthreads();
        }
    }
    // write out
    int row0 = blockIdx.y*128 + wm*32 + (lane >> 2);
    int col0 = blockIdx.x*64 + wn*32 + 2*(lane & 3);
#pragma unroll
    for (int m = 0; m < 2; m++)
#pragma unroll
        for (int n = 0; n < 4; n++) {
            int cg = col0 + n*8;
            float b0 = bias[cg], b1 = bias[cg+1];
            int r0 = row0 + m*16;
            *(float2*)(g_U + (size_t)r0*D + cg) = make_float2(acc[m][n][0]+b0, acc[m][n][1]+b1);
            *(float2*)(g_U + (size_t)(r0+8)*D + cg) = make_float2(acc[m][n][2]+b0, acc[m][n][3]+b1);
        }
}

__global__ __launch_bounds__(256)
void k_epilogue(float* __restrict__ out) {
    __shared__ float sM[D * NL2];
    __shared__ float sd[NL2];
    __shared__ int si1;
    int b = blockIdx.x;
    int tid = threadIdx.x;
    int lane = tid & 31;
    int w = tid >> 5;
    if (tid == 0) si1 = g_idx1[b];
    __syncthreads();
    int i1 = si1;
    {
        const float4* src = (const float4*)(g_Mall + (size_t)i1 * D * NL2);
        float4* dst = (float4*)sM;
        for (int t = tid; t < D * NL2 / 4; t += 256) dst[t] = src[t];
        if (tid < NL2) sd[tid] = g_dall[i1 * NL2 + tid];
    }
    __syncthreads();
    int rowBase = b * TLEN + blockIdx.y * 128 + w * 16;
    for (int r = 0; r < 16; r++) {
        int row = rowBase + r;
        const float4* up = (const float4*)(g_U + (size_t)row * D);
        float4 u0 = up[lane];
        float4 u1 = up[lane + 32];
        float h[8] = {u0.x, u0.y, u0.z, u0.w, u1.x, u1.y, u1.z, u1.w};
        float s = 0.f, q = 0.f;
#pragma unroll
        for (int e = 0; e < 8; e++) { s += h[e]; q += h[e]*h[e]; }
#pragma unroll
        for (int off = 16; off; off >>= 1) {
            s += __shfl_xor_sync(0xffffffffu, s, off);
            q += __shfl_xor_sync(0xffffffffu, q, off);
        }
        float mean = s * (1.f / 256.f);
        float var = q * (1.f / 256.f) - mean * mean;
        float rinv = rsqrtf(fmaxf(var, 0.f) + 1e-5f);
#pragma unroll
        for (int e = 0; e < 8; e++) h[e] = fmaxf((h[e] - mean) * rinv, 0.f);
        float acc = sd[lane];
#pragma unroll
        for (int e = 0; e < 8; e++) {
            int cb = (e < 4) ? e : (e + 124);
#pragma unroll 8
            for (int srcl = 0; srcl < 32; srcl++) {
                float hv = __shfl_sync(0xffffffffu, h[e], srcl);
                acc += hv * sM[(srcl * 4 + cb) * NL2 + lane];
            }
        }
        float best = acc; int bidx = lane;
#pragma unroll
        for (int off = 16; off; off >>= 1) {
            float ov = __shfl_xor_sync(0xffffffffu, best, off);
            int   oi = __shfl_xor_sync(0xffffffffu, bidx, off);
            if (ov > best || (ov == best && oi < bidx)) { best = ov; bidx = oi; }
        }
        float second = (lane == bidx) ? -1e30f : acc;
#pragma unroll
        for (int off = 16; off; off >>= 1)
            second = fmaxf(second, __shfl_xor_sync(0xffffffffu, second, off));
        if (lane == 0 && (best - second) < 0.01f * fmaxf(1.f, fabsf(best))) {
            int p = atomicAdd(&g_rcount, 1);
            g_rlist[p] = row;
        }
        const float4* trow = (const float4*)(g_table + (size_t)(i1 * NL2 + bidx) * D);
        float4* orow = (float4*)(out + (size_t)row * D);
        orow[lane]      = trow[lane];
        orow[lane + 32] = trow[lane + 32];
    }
}

// exact fp32 recompute for margin-flagged tokens (8 tokens per block chunk)
__global__ __launch_bounds__(256)
void k_repair(const float* __restrict__ x, const float* __restrict__ bl1,
              float* __restrict__ out) {
    __shared__ float xs[8][DIN];
    __shared__ float hs[8][D + 1];
    __shared__ int rows[8];
    __shared__ float sred[16];
    int tid = threadIdx.x, lane = tid & 31, w = tid >> 5;
    int total = g_rcount;
    for (int base = blockIdx.x * 8; base < total; base += gridDim.x * 8) {
        int cnt = min(8, total - base);
        __syncthreads();
        if (tid < 8) rows[tid] = (tid < cnt) ? g_rlist[base + tid] : g_rlist[base];
        __syncthreads();
#pragma unroll
        for (int i = 0; i < 8; i++) {
            const float4* src = (const float4*)(x + (size_t)rows[i] * DIN);
            float4* dst = (float4*)xs[i];
            if (tid < DIN/4) dst[tid] = src[tid];
        }
        __syncthreads();
        float a[8];
#pragma unroll
        for (int i = 0; i < 8; i++) a[i] = 0.f;
        for (int r = 0; r < DIN; r++) {
            float wv = g_Wl1T[r*D + tid];
#pragma unroll
            for (int i = 0; i < 8; i++) a[i] += xs[i][r] * wv;
        }
        float bl = bl1[tid];
#pragma unroll
        for (int i = 0; i < 8; i++) {
            float v = a[i] + bl;
            float mean, rinv;
            blockLN256(v, tid, sred, mean, rinv);
            hs[i][tid] = fmaxf((v - mean) * rinv, 0.f);
        }
        __syncthreads();
        if (w < cnt) {
            int row = rows[w];
            int i1 = g_idx1[row / TLEN];
            float acc = g_dall[i1*NL2 + lane];
            const float* M = g_Mall + (size_t)i1 * D * NL2;
            for (int c = 0; c < D; c++) acc += hs[w][c] * M[c*NL2 + lane];
            float best = acc; int bidx = lane;
#pragma unroll
            for (int off = 16; off; off >>= 1) {
                float ov = __shfl_xor_sync(0xffffffffu, best, off);
                int   oi = __shfl_xor_sync(0xffffffffu, bidx, off);
                if (ov > best || (ov == best && oi < bidx)) { best = ov; bidx = oi; }
            }
            const float4* trow = (const float4*)(g_table + (size_t)(i1*NL2 + bidx) * D);
            float4* orow = (float4*)(out + (size_t)row * D);
#pragma unroll
            for (int e = 0; e < 2; e++) orow[lane + e*32] = trow[lane + e*32];
        }
        __syncthreads();
    }
}

extern "C" void kernel_launch(void* const* d_in, const int* in_sizes, int n_in,
                              void* d_out, int out_size) {
    const float* x   = (const float*)d_in[0];
    const float* Wg1 = (const float*)d_in[1];
    const float* bg1 = (const float*)d_in[2];
    const float* Wg2 = (const float*)d_in[3];
    const float* bg2 = (const float*)d_in[4];
    const float* Wl1 = (const float*)d_in[5];
    const float* bl1 = (const float*)d_in[6];
    const float* Wl2 = (const float*)d_in[7];
    const float* bl2 = (const float*)d_in[8];
    const float* Wp  = (const float*)d_in[9];
    const float* bp  = (const float*)d_in[10];
    const float* cb1 = (const float*)d_in[11];
    const float* Wtb = (const float*)d_in[12];
    const float* btb = (const float*)d_in[13];
    const float* Wfb = (const float*)d_in[14];
    const float* bfb = (const float*)d_in[15];
    const float* cb2 = (const float*)d_in[16];
    const float* Wf  = (const float*)d_in[17];
    const float* bf  = (const float*)d_in[18];
    float* out = (float*)d_out;

    static int smem_set = 0;
    if (!smem_set) {
        cudaFuncSetAttribute(k_gemm, cudaFuncAttributeMaxDynamicSharedMemorySize, 61440);
        smem_set = 1;
    }

    float *dWl1T, *dWg1T, *dWg2T, *dWpT, *dWfbT, *dWfT;
    cudaGetSymbolAddress((void**)&dWl1T, g_Wl1T);
    cudaGetSymbolAddress((void**)&dWg1T, g_Wg1T);
    cudaGetSymbolAddress((void**)&dWg2T, g_Wg2T);
    cudaGetSymbolAddress((void**)&dWpT,  g_WpT);
    cudaGetSymbolAddress((void**)&dWfbT, g_WfbT);
    cudaGetSymbolAddress((void**)&dWfT,  g_WfT);

    k_init<<<1, 32>>>();
    dim3 tb(32, 8);
    k_transpose<<<dim3(DIN/32, D/32), tb>>>(Wl1, dWl1T, D, DIN);
    k_transpose<<<dim3(DIN/32, D/32), tb>>>(Wg1, dWg1T, D, DIN);
    k_transpose<<<dim3(D/32, DG/32), tb>>>(Wg2, dWg2T, DG, D);
    k_transpose<<<dim3(DG/32, DG/32), tb>>>(Wp, dWpT, DG, DG);
    k_transpose<<<dim3(DB/32, D/32), tb>>>(Wfb, dWfbT, D, DB);
    k_transpose<<<dim3((D+DG)/32, D/32), tb>>>(Wf, dWfT, D, D+DG);
    k_wc   <<<64, 256>>>(Wtb, Wl2, bl2, btb);
    k_nck  <<<256, 64>>>(cb2);
    k_Md   <<<dim3(8, 32), 256>>>();
    k_table<<<256, 256>>>(cb2, bfb, cb1, bf);
    k_gs1  <<<256, 256>>>(x);
    k_gs2  <<<64, 256>>>();
    k_global<<<16, 256>>>(bg1, bg2, bp, cb1);
    k_gemm <<<dim3(4, 256), 256, 61440>>>(x, Wl1, bl1);
    k_epilogue<<<dim3(16, 16), 256>>>(out);
    k_repair<<<148, 256>>>(x, bl1, out);
}